// round 5
// baseline (speedup 1.0000x reference)
#include <cuda_runtime.h>
#include <cuda_fp16.h>

#define HD   160
#define PLN  25600          // W*D
#define VOL  4096000        // H*W*D
#define NVOX 8192000ULL     // 2*160^3
#define WCH  32             // passA w-chunk
#define SEG  80             // passB/passC segment length
#define NBBC 640            // passC grid blocks: 2*160*2

// Normalized 1D Gaussian, KS=11, sigma=1.5
__device__ constexpr float GW[11] = {
    0.00102838f, 0.00759876f, 0.03600077f, 0.10936070f, 0.21300553f,
    0.26601172f,
    0.21300553f, 0.10936070f, 0.03600077f, 0.00759876f, 0.00102838f
};

constexpr float C1f  = 1.0e-4f;
constexpr float C2f  = 9.0e-4f;
constexpr float EPSf = 1.0e-12f;

// fp16 scratch: gA = D-blurred fields, gB = D+W-blurred fields.
__device__ __half gA[5ULL * NVOX];
__device__ __half gB[5ULL * NVOX];
__device__ double g_acc;            // zero-init; reset by last passC block
__device__ unsigned int g_ticket;

__device__ __forceinline__ int refl(int i) {
    return (i < 0) ? -i : ((i > HD - 1) ? (2 * (HD - 1) - i) : i);
}

// ---------------------------------------------------------------------------
// Pass A: D-blur (contiguous axis). Block = (w-chunk 32, h, b), 160 threads.
// Raw s,r rows in padded smem (172), generate 5 fields on the fly.
// ---------------------------------------------------------------------------
__global__ void __launch_bounds__(HD) passA(const float* __restrict__ src,
                                            const float* __restrict__ ref) {
    __shared__ float S[WCH][172];
    __shared__ float R[WCH][172];

    const int d  = threadIdx.x;
    const int b  = blockIdx.z;
    const int h  = blockIdx.y;
    const int w0 = blockIdx.x * WCH;

    const size_t bh = ((size_t)(b * HD + h)) * PLN;

    for (int row = 0; row < WCH; ++row) {
        const float* ps = src + bh + (size_t)(w0 + row) * HD;
        const float* pr = ref + bh + (size_t)(w0 + row) * HD;
        S[row][6 + d] = __ldg(ps + d);
        R[row][6 + d] = __ldg(pr + d);
        if (d < 6)    { S[row][d]      = __ldg(ps + 6 - d);   R[row][d]      = __ldg(pr + 6 - d); }
        if (d >= 154) { S[row][d + 12] = __ldg(ps + 312 - d); R[row][d + 12] = __ldg(pr + 312 - d); }
    }
    __syncthreads();

    for (int row = 0; row < WCH; ++row) {
        float a0 = 0.f, a1 = 0.f, a2 = 0.f, a3 = 0.f, a4 = 0.f;
        #pragma unroll
        for (int k = 0; k < 11; ++k) {
            const float s  = S[row][d + 1 + k];
            const float v  = R[row][d + 1 + k];
            const float ss = s * s, vv = v * v, sv = s * v;
            a0 = fmaf(GW[k], s,  a0);
            a1 = fmaf(GW[k], v,  a1);
            a2 = fmaf(GW[k], ss, a2);
            a3 = fmaf(GW[k], vv, a3);
            a4 = fmaf(GW[k], sv, a4);
        }
        const size_t off = bh + (size_t)(w0 + row) * HD + d;
        gA[0ULL * NVOX + off] = __float2half_rn(a0);
        gA[1ULL * NVOX + off] = __float2half_rn(a1);
        gA[2ULL * NVOX + off] = __float2half_rn(a2);
        gA[3ULL * NVOX + off] = __float2half_rn(a3);
        gA[4ULL * NVOX + off] = __float2half_rn(a4);
    }
}

// ---------------------------------------------------------------------------
// Pass B: W-blur. Block = (w-segment 80, h, b), 160 threads.
// 12-slot smem plane ring (5 fields x 160 d, fp32) -> one sync per iter.
// slot(plane p) = (p + 5) % 12. Iter w reads slots (w..w+10)%12, loads
// plane w+6 into slot (w+11)%12 (never read this iter).
// ---------------------------------------------------------------------------
__global__ void __launch_bounds__(HD) passB() {
    __shared__ float ring[5][12][HD];   // 38.4 KB

    const int d  = threadIdx.x;
    const int b  = blockIdx.z;
    const int h  = blockIdx.y;
    const int w0 = blockIdx.x * SEG;

    const size_t bh = ((size_t)(b * HD + h)) * PLN;

    // warm-up: planes w0-5 .. w0+5
    for (int j = 0; j < 11; ++j) {
        const int pq = refl(w0 - 5 + j);
        const int slot = (w0 + j) % 12;
        for (int i = d; i < 400; i += HD) {
            const int f = i / 80, e = i - f * 80;
            const __half2 hv = *reinterpret_cast<const __half2*>(
                gA + (size_t)f * NVOX + bh + (size_t)pq * HD + 2 * e);
            const float2 fv = __half22float2(hv);
            ring[f][slot][2 * e]     = fv.x;
            ring[f][slot][2 * e + 1] = fv.y;
        }
    }

    for (int w = w0; w < w0 + SEG; ++w) {
        __syncthreads();
        {   // prefetch plane w+6 into slot (w+11)%12
            const int pq = refl(w + 6);
            const int slot = (w + 11) % 12;
            for (int i = d; i < 400; i += HD) {
                const int f = i / 80, e = i - f * 80;
                const __half2 hv = *reinterpret_cast<const __half2*>(
                    gA + (size_t)f * NVOX + bh + (size_t)pq * HD + 2 * e);
                const float2 fv = __half22float2(hv);
                ring[f][slot][2 * e]     = fv.x;
                ring[f][slot][2 * e + 1] = fv.y;
            }
        }
        float o0 = 0.f, o1 = 0.f, o2 = 0.f, o3 = 0.f, o4 = 0.f;
        #pragma unroll
        for (int k = 0; k < 11; ++k) {
            const int sl = (w + k) % 12;
            o0 = fmaf(GW[k], ring[0][sl][d], o0);
            o1 = fmaf(GW[k], ring[1][sl][d], o1);
            o2 = fmaf(GW[k], ring[2][sl][d], o2);
            o3 = fmaf(GW[k], ring[3][sl][d], o3);
            o4 = fmaf(GW[k], ring[4][sl][d], o4);
        }
        const size_t off = bh + (size_t)w * HD + d;
        gB[0ULL * NVOX + off] = __float2half_rn(o0);
        gB[1ULL * NVOX + off] = __float2half_rn(o1);
        gB[2ULL * NVOX + off] = __float2half_rn(o2);
        gB[3ULL * NVOX + off] = __float2half_rn(o3);
        gB[4ULL * NVOX + off] = __float2half_rn(o4);
    }
}

// ---------------------------------------------------------------------------
// Pass C: H-blur + SSIM + reduce. Block = (h-segment 80, w, b), 160 threads.
// Same 12-slot ring pattern over h-planes of gB.
// ---------------------------------------------------------------------------
__global__ void __launch_bounds__(HD) passC(float* __restrict__ out) {
    __shared__ float ring[5][12][HD];

    const int d  = threadIdx.x;
    const int b  = blockIdx.z;
    const int w  = blockIdx.y;
    const int h0 = blockIdx.x * SEG;

    const size_t bw = (size_t)b * VOL + (size_t)w * HD;

    for (int j = 0; j < 11; ++j) {
        const int pq = refl(h0 - 5 + j);
        const int slot = (h0 + j) % 12;
        for (int i = d; i < 400; i += HD) {
            const int f = i / 80, e = i - f * 80;
            const __half2 hv = *reinterpret_cast<const __half2*>(
                gB + (size_t)f * NVOX + bw + (size_t)pq * PLN + 2 * e);
            const float2 fv = __half22float2(hv);
            ring[f][slot][2 * e]     = fv.x;
            ring[f][slot][2 * e + 1] = fv.y;
        }
    }

    float acc = 0.f;

    for (int hh = h0; hh < h0 + SEG; ++hh) {
        __syncthreads();
        {
            const int pq = refl(hh + 6);
            const int slot = (hh + 11) % 12;
            for (int i = d; i < 400; i += HD) {
                const int f = i / 80, e = i - f * 80;
                const __half2 hv = *reinterpret_cast<const __half2*>(
                    gB + (size_t)f * NVOX + bw + (size_t)pq * PLN + 2 * e);
                const float2 fv = __half22float2(hv);
                ring[f][slot][2 * e]     = fv.x;
                ring[f][slot][2 * e + 1] = fv.y;
            }
        }
        float mu1 = 0.f, mu2 = 0.f, m11 = 0.f, m22 = 0.f, m12 = 0.f;
        #pragma unroll
        for (int k = 0; k < 11; ++k) {
            const int sl = (hh + k) % 12;
            mu1 = fmaf(GW[k], ring[0][sl][d], mu1);
            mu2 = fmaf(GW[k], ring[1][sl][d], mu2);
            m11 = fmaf(GW[k], ring[2][sl][d], m11);
            m22 = fmaf(GW[k], ring[3][sl][d], m22);
            m12 = fmaf(GW[k], ring[4][sl][d], m12);
        }
        const float a  = mu1 * mu1;
        const float bb = mu2 * mu2;
        const float c  = mu1 * mu2;
        const float s1 = m11 - a, s2 = m22 - bb, s12 = m12 - c;
        const float num = (2.f * c + C1f) * (2.f * s12 + C2f);
        const float den = (a + bb + C1f) * (s1 + s2 + C2f);
        acc += __fdividef(num, den + EPSf);
    }

    // Reduce: 5 warps -> smem -> atomicAdd(double), ticket finalize.
    float v = acc;
    #pragma unroll
    for (int o = 16; o > 0; o >>= 1) v += __shfl_down_sync(0xffffffffu, v, o);
    __shared__ float ws[5];
    if ((threadIdx.x & 31) == 0) ws[threadIdx.x >> 5] = v;
    __syncthreads();
    if (threadIdx.x == 0) {
        const float s = ws[0] + ws[1] + ws[2] + ws[3] + ws[4];
        atomicAdd(&g_acc, (double)s);
        __threadfence();
        const unsigned done = atomicAdd(&g_ticket, 1u);
        if (done == NBBC - 1) {
            const double vv = atomicAdd(&g_acc, 0.0);
            out[0] = (float)(1.0 - vv / (double)NVOX);
            g_acc = 0.0;
            g_ticket = 0u;
            __threadfence();
        }
    }
}

extern "C" void kernel_launch(void* const* d_in, const int* in_sizes, int n_in,
                              void* d_out, int out_size) {
    const float* src = (const float*)d_in[0];
    const float* ref = (const float*)d_in[1];
    float* out = (float*)d_out;

    passA<<<dim3(HD / WCH, HD, 2), HD>>>(src, ref);
    passB<<<dim3(HD / SEG, HD, 2), HD>>>();
    passC<<<dim3(HD / SEG, HD, 2), HD>>>(out);
}

// round 6
// speedup vs baseline: 2.3055x; 2.3055x over previous
#include <cuda_runtime.h>
#include <cuda_fp16.h>

#define HD   160
#define PLN  25600          // W*D
#define VOL  4096000        // H*W*D
#define NVOX 8192000ULL     // 2*160^3
#define WCH  16             // P1 w-rows per block
#define SEG  40             // P2/P3 slide segment
#define NBBC 1280           // P3 grid blocks: 4*160*2

// Normalized 1D Gaussian, KS=11, sigma=1.5
__device__ constexpr float GW[11] = {
    0.00102838f, 0.00759876f, 0.03600077f, 0.10936070f, 0.21300553f,
    0.26601172f,
    0.21300553f, 0.10936070f, 0.03600077f, 0.00759876f, 0.00102838f
};

constexpr float C1f  = 1.0e-4f;
constexpr float C2f  = 9.0e-4f;
constexpr float EPSf = 1.0e-12f;

// fp16 scratch: gA = D-blurred fields, gC = D+W-blurred fields.
__device__ __half gA[5ULL * NVOX];
__device__ __half gC[5ULL * NVOX];
__device__ double g_acc;
__device__ unsigned int g_ticket;

__device__ __forceinline__ int refl(int i) {
    return (i < 0) ? -i : ((i > HD - 1) ? (2 * (HD - 1) - i) : i);
}

// ---------------------------------------------------------------------------
// P1: D-blur + product fields. Block (w-chunk 16, h, b), 160 threads.
// Raw rows in padded smem; each thread handles a d-pair via a 14-float
// register window (7 LDS.64). Products shared within the pair.
// ---------------------------------------------------------------------------
__global__ void __launch_bounds__(HD) passD(const float* __restrict__ src,
                                            const float* __restrict__ ref) {
    __shared__ float S[WCH][172];
    __shared__ float R[WCH][172];

    const int t  = threadIdx.x;
    const int b  = blockIdx.z;
    const int h  = blockIdx.y;
    const int w0 = blockIdx.x * WCH;

    const size_t bh = ((size_t)(b * HD + h)) * PLN;

    for (int row = 0; row < WCH; ++row) {
        const float* ps = src + bh + (size_t)(w0 + row) * HD;
        const float* pr = ref + bh + (size_t)(w0 + row) * HD;
        S[row][6 + t] = __ldg(ps + t);
        R[row][6 + t] = __ldg(pr + t);
        if (t < 6)    { S[row][t]      = __ldg(ps + 6 - t);   R[row][t]      = __ldg(pr + 6 - t); }
        if (t >= 154) { S[row][t + 12] = __ldg(ps + 312 - t); R[row][t + 12] = __ldg(pr + 312 - t); }
    }
    __syncthreads();

    const int rp = t / 80;          // which row of each pair
    const int tp = t % 80;          // d-pair index

    for (int it = 0; it < WCH / 2; ++it) {
        const int row = it * 2 + rp;
        // Register window: W[i] = smem[2*tp + i], i=0..13 (global d' = 2tp+i-6)
        float ws[14], wr[14];
        const float2* s2 = reinterpret_cast<const float2*>(&S[row][0]) + tp;
        const float2* r2 = reinterpret_cast<const float2*>(&R[row][0]) + tp;
        #pragma unroll
        for (int p = 0; p < 7; ++p) {
            const float2 a = s2[p]; ws[2 * p] = a.x; ws[2 * p + 1] = a.y;
            const float2 c = r2[p]; wr[2 * p] = c.x; wr[2 * p + 1] = c.y;
        }

        // voxel x = d=2tp uses W[1+k]; voxel y = d=2tp+1 uses W[2+k]
        float a0x = 0.f, a1x = 0.f, a2x = 0.f, a3x = 0.f, a4x = 0.f;
        float a0y = 0.f, a1y = 0.f, a2y = 0.f, a3y = 0.f, a4y = 0.f;

        #pragma unroll
        for (int k = 0; k < 11; ++k) {           // element W[1+k]
            const float s = ws[1 + k], v = wr[1 + k];
            const float ss = s * s, vv = v * v, sv = s * v;
            a0x = fmaf(GW[k], s,  a0x);
            a1x = fmaf(GW[k], v,  a1x);
            a2x = fmaf(GW[k], ss, a2x);
            a3x = fmaf(GW[k], vv, a3x);
            a4x = fmaf(GW[k], sv, a4x);
            if (k >= 1) {
                a0y = fmaf(GW[k - 1], s,  a0y);
                a1y = fmaf(GW[k - 1], v,  a1y);
                a2y = fmaf(GW[k - 1], ss, a2y);
                a3y = fmaf(GW[k - 1], vv, a3y);
                a4y = fmaf(GW[k - 1], sv, a4y);
            }
        }
        {   // element W[12] (voxel y, tap 10)
            const float s = ws[12], v = wr[12];
            const float ss = s * s, vv = v * v, sv = s * v;
            a0y = fmaf(GW[10], s,  a0y);
            a1y = fmaf(GW[10], v,  a1y);
            a2y = fmaf(GW[10], ss, a2y);
            a3y = fmaf(GW[10], vv, a3y);
            a4y = fmaf(GW[10], sv, a4y);
        }

        const size_t hoff = (bh + (size_t)(w0 + row) * HD) / 2 + tp;  // half2 index
        reinterpret_cast<__half2*>(gA + 0ULL * NVOX)[hoff] = __floats2half2_rn(a0x, a0y);
        reinterpret_cast<__half2*>(gA + 1ULL * NVOX)[hoff] = __floats2half2_rn(a1x, a1y);
        reinterpret_cast<__half2*>(gA + 2ULL * NVOX)[hoff] = __floats2half2_rn(a2x, a2y);
        reinterpret_cast<__half2*>(gA + 3ULL * NVOX)[hoff] = __floats2half2_rn(a3x, a3y);
        reinterpret_cast<__half2*>(gA + 4ULL * NVOX)[hoff] = __floats2half2_rn(a4x, a4y);
    }
}

// ---------------------------------------------------------------------------
// P2: W-blur. Thread owns (b,h,d), slides w over SEG with an 11-slot fp32
// register ring. Slot indices static via 11-unrolled inner loop.
// ---------------------------------------------------------------------------
__global__ void __launch_bounds__(HD) passW() {
    const int d  = threadIdx.x;
    const int b  = blockIdx.z;
    const int h  = blockIdx.y;
    const int w0 = blockIdx.x * SEG;

    const size_t bh = ((size_t)(b * HD + h)) * PLN;

    float win[5][11];

    #pragma unroll
    for (int m = 0; m < 10; ++m) {              // planes w0-5 .. w0+4 -> slot m
        const size_t off = bh + (size_t)refl(w0 - 5 + m) * HD + d;
        #pragma unroll
        for (int f = 0; f < 5; ++f)
            win[f][m] = __half2float(__ldg(gA + (size_t)f * NVOX + off));
    }

    #pragma unroll 1
    for (int c = 0; c < SEG / 11 + 1; ++c) {
        const int jbase = c * 11;
        #pragma unroll
        for (int u = 0; u < 11; ++u) {
            const int j = jbase + u;
            if (j >= SEG) break;                 // tail (u static, j runtime)
            {   // load plane w0+j+5 into slot (u+10)%11
                const size_t off = bh + (size_t)refl(w0 + j + 5) * HD + d;
                #pragma unroll
                for (int f = 0; f < 5; ++f)
                    win[f][(u + 10) % 11] =
                        __half2float(__ldg(gA + (size_t)f * NVOX + off));
            }
            float o0 = 0.f, o1 = 0.f, o2 = 0.f, o3 = 0.f, o4 = 0.f;
            #pragma unroll
            for (int k = 0; k < 11; ++k) {
                const int sl = (u + k) % 11;
                o0 = fmaf(GW[k], win[0][sl], o0);
                o1 = fmaf(GW[k], win[1][sl], o1);
                o2 = fmaf(GW[k], win[2][sl], o2);
                o3 = fmaf(GW[k], win[3][sl], o3);
                o4 = fmaf(GW[k], win[4][sl], o4);
            }
            const size_t oo = bh + (size_t)(w0 + j) * HD + d;
            gC[0ULL * NVOX + oo] = __float2half_rn(o0);
            gC[1ULL * NVOX + oo] = __float2half_rn(o1);
            gC[2ULL * NVOX + oo] = __float2half_rn(o2);
            gC[3ULL * NVOX + oo] = __float2half_rn(o3);
            gC[4ULL * NVOX + oo] = __float2half_rn(o4);
        }
    }
}

// ---------------------------------------------------------------------------
// P3: H-blur + SSIM + reduce. Same ring pattern sliding h (stride PLN).
// ---------------------------------------------------------------------------
__global__ void __launch_bounds__(HD) passH(float* __restrict__ out) {
    const int d  = threadIdx.x;
    const int b  = blockIdx.z;
    const int w  = blockIdx.y;
    const int h0 = blockIdx.x * SEG;

    const size_t bw = (size_t)b * VOL + (size_t)w * HD + d;

    float win[5][11];

    #pragma unroll
    for (int m = 0; m < 10; ++m) {
        const size_t off = bw + (size_t)refl(h0 - 5 + m) * PLN;
        #pragma unroll
        for (int f = 0; f < 5; ++f)
            win[f][m] = __half2float(__ldg(gC + (size_t)f * NVOX + off));
    }

    float acc = 0.f;

    #pragma unroll 1
    for (int c = 0; c < SEG / 11 + 1; ++c) {
        const int jbase = c * 11;
        #pragma unroll
        for (int u = 0; u < 11; ++u) {
            const int j = jbase + u;
            if (j >= SEG) break;
            {
                const size_t off = bw + (size_t)refl(h0 + j + 5) * PLN;
                #pragma unroll
                for (int f = 0; f < 5; ++f)
                    win[f][(u + 10) % 11] =
                        __half2float(__ldg(gC + (size_t)f * NVOX + off));
            }
            float mu1 = 0.f, mu2 = 0.f, m11 = 0.f, m22 = 0.f, m12 = 0.f;
            #pragma unroll
            for (int k = 0; k < 11; ++k) {
                const int sl = (u + k) % 11;
                mu1 = fmaf(GW[k], win[0][sl], mu1);
                mu2 = fmaf(GW[k], win[1][sl], mu2);
                m11 = fmaf(GW[k], win[2][sl], m11);
                m22 = fmaf(GW[k], win[3][sl], m22);
                m12 = fmaf(GW[k], win[4][sl], m12);
            }
            const float a  = mu1 * mu1;
            const float bb = mu2 * mu2;
            const float cc = mu1 * mu2;
            const float s1 = m11 - a, s2 = m22 - bb, s12 = m12 - cc;
            const float num = (2.f * cc + C1f) * (2.f * s12 + C2f);
            const float den = (a + bb + C1f) * (s1 + s2 + C2f);
            acc += __fdividef(num, den + EPSf);
        }
    }

    // Reduce: 5 warps -> smem -> atomicAdd(double), ticket finalize.
    float v = acc;
    #pragma unroll
    for (int o = 16; o > 0; o >>= 1) v += __shfl_down_sync(0xffffffffu, v, o);
    __shared__ float ws[5];
    if ((threadIdx.x & 31) == 0) ws[threadIdx.x >> 5] = v;
    __syncthreads();
    if (threadIdx.x == 0) {
        const float s = ws[0] + ws[1] + ws[2] + ws[3] + ws[4];
        atomicAdd(&g_acc, (double)s);
        __threadfence();
        const unsigned done = atomicAdd(&g_ticket, 1u);
        if (done == NBBC - 1) {
            const double vv = atomicAdd(&g_acc, 0.0);
            out[0] = (float)(1.0 - vv / (double)NVOX);
            g_acc = 0.0;
            g_ticket = 0u;
            __threadfence();
        }
    }
}

extern "C" void kernel_launch(void* const* d_in, const int* in_sizes, int n_in,
                              void* d_out, int out_size) {
    const float* src = (const float*)d_in[0];
    const float* ref = (const float*)d_in[1];
    float* out = (float*)d_out;

    passD<<<dim3(HD / WCH, HD, 2), HD>>>(src, ref);
    passW<<<dim3(HD / SEG, HD, 2), HD>>>();
    passH<<<dim3(HD / SEG, HD, 2), HD>>>(out);
}